// round 1
// baseline (speedup 1.0000x reference)
#include <cuda_runtime.h>
#include <math.h>

#define NP    65534
#define NTOK  (NP*4)          // 262136 tokens
#define GH    180
#define GW    360
#define NCELL (GH*GW)         // 64800
#define CLN   512

// ---------------- scratch (device globals: no allocation allowed) ----------------
__device__ float g_feat[(size_t)NP*80];      // 75 used, ld=80
__device__ int   g_flat[NP];
__device__ float g_h   [(size_t)NTOK*128];   // transformer state (N,4,128)
__device__ float g_a   [(size_t)NTOK*128];   // LN output
__device__ float g_qkv [(size_t)NTOK*384];
__device__ float g_o   [(size_t)NTOK*128];
__device__ float g_gel [(size_t)NTOK*512];
__device__ float g_y   [(size_t)NP*512];
__device__ float g_cnt [NCELL];

// ---------------- feature build + grid index ----------------
__global__ void feat_kernel(const float* __restrict__ x) {
    int i = blockIdx.x * blockDim.x + threadIdx.x;
    if (i >= NP) return;
    const float* xr = x + (size_t)i * 24;
    float lat = xr[0];
    if (lat == -90.0f) lat += 0.0001f;
    float lon = xr[1];
    float t   = xr[2];

    int lati = (int)floorf(90.0f - lat);
    int loni = (int)fmodf(180.0f + floorf(lon + 180.0f), 360.0f);
    g_flat[i] = lati * GW + loni;

    float* f = g_feat + (size_t)i * 80;
    f[0] = lat * (1.0f/90.0f);
    f[1] = lon * (1.0f/180.0f);
    f[2] = t   * (1.0f/12.0f);
    #pragma unroll
    for (int j = 3; j < 24; j++) f[j] = xr[j];

    float p0 = -lat - floorf(-lat);   // mod(-lat, 1)
    float p1 =  lon - floorf(lon);    // mod(lon, 1)
    float p2 =  t + 1.0f;
    f[24] = p0; f[25] = p1; f[26] = p2;
    float p[3] = {p0, p1, p2};
    #pragma unroll
    for (int c = 0; c < 3; c++) {
        float fr = 3.14159274101257324f;  // fp32 pi; *2^k stays exact
        #pragma unroll
        for (int k = 0; k < 8; k++) {
            float ang = p[c] * fr;
            f[27 + c*8 + k] = sinf(ang);
            f[51 + c*8 + k] = cosf(ang);
            fr *= 2.0f;
        }
    }
}

// ---------------- generic fp32 GEMM: C = A(MxK)@B(KxN) + bias, epilogues ----------------
// EPI: 0 = bias only, 1 = bias + residual (R), 2 = bias + tanh-GELU
// Tile: 128x128x8, 256 threads, 8x8 per-thread. N must be a multiple of 128 (true here).
template<int EPI>
__global__ void sgemm128(const float* __restrict__ A, const float* __restrict__ B,
                         const float* __restrict__ bias, const float* __restrict__ R,
                         float* __restrict__ C, int M, int N, int K, int lda) {
    __shared__ float As[8][132];
    __shared__ float Bs[8][132];
    const int bm = blockIdx.y * 128;
    const int bn = blockIdx.x * 128;
    const int tid = threadIdx.x;
    const int tx = tid & 15;    // 16 cols of threads
    const int ty = tid >> 4;    // 16 rows of threads

    float acc[8][8];
    #pragma unroll
    for (int i = 0; i < 8; i++)
        #pragma unroll
        for (int j = 0; j < 8; j++) acc[i][j] = 0.0f;

    for (int k0 = 0; k0 < K; k0 += 8) {
        // load A tile 128x8 -> As[k][m]
        #pragma unroll
        for (int l = 0; l < 4; l++) {
            int idx = tid + l * 256;          // 0..1023
            int m = idx >> 3, k = idx & 7;
            int gm = bm + m, gk = k0 + k;
            float v = 0.0f;
            if (gm < M && gk < K) v = A[(size_t)gm * lda + gk];
            As[k][m] = v;
        }
        // load B tile 8x128 -> Bs[k][n]
        #pragma unroll
        for (int l = 0; l < 4; l++) {
            int idx = tid + l * 256;
            int k = idx >> 7, n = idx & 127;
            int gk = k0 + k;
            float v = 0.0f;
            if (gk < K) v = B[(size_t)gk * N + bn + n];
            Bs[k][n] = v;
        }
        __syncthreads();
        #pragma unroll
        for (int kk = 0; kk < 8; kk++) {
            float ra[8], rb[8];
            #pragma unroll
            for (int i = 0; i < 8; i++) ra[i] = As[kk][ty * 8 + i];
            #pragma unroll
            for (int j = 0; j < 8; j++) rb[j] = Bs[kk][tx * 8 + j];
            #pragma unroll
            for (int i = 0; i < 8; i++)
                #pragma unroll
                for (int j = 0; j < 8; j++) acc[i][j] += ra[i] * rb[j];
        }
        __syncthreads();
    }

    #pragma unroll
    for (int i = 0; i < 8; i++) {
        int gm = bm + ty * 8 + i;
        if (gm >= M) continue;
        #pragma unroll
        for (int j = 0; j < 8; j++) {
            int gn = bn + tx * 8 + j;
            float v = acc[i][j] + bias[gn];
            if (EPI == 1) v += R[(size_t)gm * N + gn];
            if (EPI == 2) {
                float u = v;
                v = 0.5f * u * (1.0f + tanhf(0.7978845608028654f * (u + 0.044715f * u * u * u)));
            }
            C[(size_t)gm * N + gn] = v;
        }
    }
}

// ---------------- LayerNorm: one warp per token (128 dims) ----------------
__global__ void ln_kernel(const float* __restrict__ h, float* __restrict__ out,
                          const float* __restrict__ s, const float* __restrict__ b) {
    int gthread = blockIdx.x * blockDim.x + threadIdx.x;
    int token = gthread >> 5;
    int lane  = threadIdx.x & 31;
    if (token >= NTOK) return;
    const float4* row = (const float4*)(h + (size_t)token * 128);
    float4 v = row[lane];
    float sum = v.x + v.y + v.z + v.w;
    float sq  = v.x*v.x + v.y*v.y + v.z*v.z + v.w*v.w;
    #pragma unroll
    for (int o = 16; o > 0; o >>= 1) {
        sum += __shfl_xor_sync(0xffffffffu, sum, o);
        sq  += __shfl_xor_sync(0xffffffffu, sq,  o);
    }
    float mean = sum * (1.0f/128.0f);
    float var  = sq  * (1.0f/128.0f) - mean * mean;
    float r = rsqrtf(var + 1e-5f);
    float4 sv = ((const float4*)s)[lane];
    float4 bv = ((const float4*)b)[lane];
    float4 o4;
    o4.x = (v.x - mean) * r * sv.x + bv.x;
    o4.y = (v.y - mean) * r * sv.y + bv.y;
    o4.z = (v.z - mean) * r * sv.z + bv.z;
    o4.w = (v.w - mean) * r * sv.w + bv.w;
    ((float4*)(out + (size_t)token * 128))[lane] = o4;
}

// ---------------- attention: one thread per (point, head); 4 tokens, dh=16 ----------------
__global__ void attn_kernel() {
    int idx = blockIdx.x * blockDim.x + threadIdx.x;
    if (idx >= NP * 8) return;
    int n = idx >> 3;
    int h = idx & 7;
    const float* base = g_qkv + (size_t)n * 1536 + h * 16;  // token stride 384
    #pragma unroll
    for (int qi = 0; qi < 4; qi++) {
        float q[16];
        const float4* qp = (const float4*)(base + qi * 384);
        #pragma unroll
        for (int c = 0; c < 4; c++) {
            float4 t = qp[c];
            q[c*4+0] = t.x; q[c*4+1] = t.y; q[c*4+2] = t.z; q[c*4+3] = t.w;
        }
        float sc[4];
        float mx = -1e30f;
        #pragma unroll
        for (int ki = 0; ki < 4; ki++) {
            const float4* kp = (const float4*)(base + 128 + ki * 384);
            float s = 0.0f;
            #pragma unroll
            for (int c = 0; c < 4; c++) {
                float4 t = kp[c];
                s += q[c*4+0]*t.x + q[c*4+1]*t.y + q[c*4+2]*t.z + q[c*4+3]*t.w;
            }
            s *= 0.25f;   // 1/sqrt(16)
            sc[ki] = s;
            mx = fmaxf(mx, s);
        }
        float sum = 0.0f;
        #pragma unroll
        for (int ki = 0; ki < 4; ki++) { sc[ki] = expf(sc[ki] - mx); sum += sc[ki]; }
        float inv = 1.0f / sum;
        float acc[16];
        #pragma unroll
        for (int d = 0; d < 16; d++) acc[d] = 0.0f;
        #pragma unroll
        for (int ki = 0; ki < 4; ki++) {
            float w = sc[ki] * inv;
            const float4* vp = (const float4*)(base + 256 + ki * 384);
            #pragma unroll
            for (int c = 0; c < 4; c++) {
                float4 t = vp[c];
                acc[c*4+0] += w * t.x; acc[c*4+1] += w * t.y;
                acc[c*4+2] += w * t.z; acc[c*4+3] += w * t.w;
            }
        }
        float4* op = (float4*)(g_o + (size_t)(n * 4 + qi) * 128 + h * 16);
        #pragma unroll
        for (int c = 0; c < 4; c++) {
            float4 t;
            t.x = acc[c*4+0]; t.y = acc[c*4+1]; t.z = acc[c*4+2]; t.w = acc[c*4+3];
            op[c] = t;
        }
    }
}

// ---------------- segment mean ----------------
__global__ void zero_kernel(float* __restrict__ out) {
    int i = blockIdx.x * blockDim.x + threadIdx.x;
    if (i < NCELL * CLN) out[i] = 0.0f;
    else if (i < NCELL * CLN + NCELL) g_cnt[i - NCELL * CLN] = 0.0f;
}

__global__ void scatter_kernel(float* __restrict__ out) {
    int idx = blockIdx.x * blockDim.x + threadIdx.x;
    if (idx >= NP * 512) return;
    int n = idx >> 9;
    int j = idx & 511;
    int cell = g_flat[n];
    atomicAdd(out + (size_t)cell * 512 + j, g_y[idx]);
    if (j == 0) atomicAdd(&g_cnt[cell], 1.0f);
}

__global__ void div_kernel(float* __restrict__ out) {
    int i = blockIdx.x * blockDim.x + threadIdx.x;
    if (i >= NCELL * 512) return;
    out[i] *= 1.0f / fmaxf(g_cnt[i >> 9], 1.0f);
}

// ---------------- driver ----------------
extern "C" void kernel_launch(void* const* d_in, const int* in_sizes, int n_in,
                              void* d_out, int out_size) {
    const float* x      = (const float*)d_in[0];
    const float* W_emb  = (const float*)d_in[1];
    const float* b_emb  = (const float*)d_in[2];
    const float* ln1_s  = (const float*)d_in[3];
    const float* ln1_b  = (const float*)d_in[4];
    const float* Wqkv   = (const float*)d_in[5];
    const float* bqkv   = (const float*)d_in[6];
    const float* Wo     = (const float*)d_in[7];
    const float* bo     = (const float*)d_in[8];
    const float* ln2_s  = (const float*)d_in[9];
    const float* ln2_b  = (const float*)d_in[10];
    const float* Wf1    = (const float*)d_in[11];
    const float* bf1    = (const float*)d_in[12];
    const float* Wf2    = (const float*)d_in[13];
    const float* bf2    = (const float*)d_in[14];
    const float* W_comb = (const float*)d_in[15];
    const float* b_comb = (const float*)d_in[16];
    float* out = (float*)d_out;

    float *p_feat, *p_h, *p_a, *p_qkv, *p_o, *p_gel, *p_y;
    cudaGetSymbolAddress((void**)&p_feat, g_feat);
    cudaGetSymbolAddress((void**)&p_h,    g_h);
    cudaGetSymbolAddress((void**)&p_a,    g_a);
    cudaGetSymbolAddress((void**)&p_qkv,  g_qkv);
    cudaGetSymbolAddress((void**)&p_o,    g_o);
    cudaGetSymbolAddress((void**)&p_gel,  g_gel);
    cudaGetSymbolAddress((void**)&p_y,    g_y);

    const int TB = 256;

    // 1) features + grid indices
    feat_kernel<<<(NP + TB - 1) / TB, TB>>>(x);

    // 2) embedding: feat(NP x 75) @ W_emb(75 x 512) -> h
    {
        dim3 grid(512 / 128, (NP + 127) / 128);
        sgemm128<0><<<grid, TB>>>(p_feat, W_emb, b_emb, nullptr, p_h, NP, 512, 75, 80);
    }

    // 3) transformer layers
    for (int i = 0; i < 2; i++) {
        // LN1
        ln_kernel<<<(NTOK * 32 + TB - 1) / TB, TB>>>(p_h, p_a, ln1_s + i * 128, ln1_b + i * 128);
        // QKV: (4N x 128) @ (128 x 384)
        {
            dim3 grid(384 / 128, (NTOK + 127) / 128);
            sgemm128<0><<<grid, TB>>>(p_a, Wqkv + (size_t)i * 128 * 384, bqkv + i * 384,
                                      nullptr, p_qkv, NTOK, 384, 128, 128);
        }
        // attention
        attn_kernel<<<(NP * 8 + TB - 1) / TB, TB>>>();
        // o-proj + residual: h = h + o @ Wo + bo
        {
            dim3 grid(1, (NTOK + 127) / 128);
            sgemm128<1><<<grid, TB>>>(p_o, Wo + (size_t)i * 128 * 128, bo + i * 128,
                                      p_h, p_h, NTOK, 128, 128, 128);
        }
        // LN2
        ln_kernel<<<(NTOK * 32 + TB - 1) / TB, TB>>>(p_h, p_a, ln2_s + i * 128, ln2_b + i * 128);
        // FF1 + GELU: (4N x 128) @ (128 x 512)
        {
            dim3 grid(512 / 128, (NTOK + 127) / 128);
            sgemm128<2><<<grid, TB>>>(p_a, Wf1 + (size_t)i * 128 * 512, bf1 + i * 512,
                                      nullptr, p_gel, NTOK, 512, 128, 128);
        }
        // FF2 + residual: h = h + g @ Wf2 + bf2
        {
            dim3 grid(1, (NTOK + 127) / 128);
            sgemm128<1><<<grid, TB>>>(p_gel, Wf2 + (size_t)i * 512 * 128, bf2 + i * 128,
                                      p_h, p_h, NTOK, 128, 512, 512);
        }
    }

    // 4) head: h(NP x 512) @ W_comb(512 x 512) -> y
    {
        dim3 grid(512 / 128, (NP + 127) / 128);
        sgemm128<0><<<grid, TB>>>(p_h, W_comb, b_comb, nullptr, p_y, NP, 512, 512, 512);
    }

    // 5) segment mean into grid
    zero_kernel<<<(NCELL * CLN + NCELL + TB - 1) / TB, TB>>>(out);
    scatter_kernel<<<(NP * 512 + TB - 1) / TB, TB>>>(out);
    div_kernel<<<(NCELL * 512 + TB - 1) / TB, TB>>>(out);
}

// round 2
// speedup vs baseline: 2.7095x; 2.7095x over previous
#include <cuda_runtime.h>
#include <math.h>
#include <stdint.h>

#define NP    65534
#define NTOK  (NP*4)          // 262136 tokens
#define GH    180
#define GW    360
#define NCELL (GH*GW)         // 64800
#define CLN   512

// ---------------- scratch (device globals: no allocation allowed) ----------------
__device__ float g_feat[(size_t)NP*80];      // 75 used + zero pad to 80
__device__ int   g_flat[NP];
__device__ float g_h   [(size_t)NTOK*128];   // transformer state (N,4,128)
__device__ float g_a   [(size_t)NTOK*128];   // LN output
__device__ float g_qkv [(size_t)NTOK*384];
__device__ float g_o   [(size_t)NTOK*128];
__device__ float g_gel [(size_t)NTOK*512];
__device__ float g_y   [(size_t)NP*512];
__device__ float g_cnt [NCELL];
__device__ float g_wt  [696320];             // transposed, tf32-rounded weights

// ---------------- small PTX helpers ----------------
__device__ __forceinline__ uint32_t f2tf32(float x) {
    uint32_t r;
    asm("cvt.rna.tf32.f32 %0, %1;" : "=r"(r) : "f"(x));
    return r;
}

__device__ __forceinline__ void cpasync16(uint32_t dst, const float* src, bool pred) {
    int sz = pred ? 16 : 0;
    asm volatile("cp.async.cg.shared.global [%0], [%1], 16, %2;\n"
                 :: "r"(dst), "l"(src), "r"(sz));
}
__device__ __forceinline__ void cp_commit() {
    asm volatile("cp.async.commit_group;\n" ::);
}
__device__ __forceinline__ void ldm4(uint32_t& r0, uint32_t& r1, uint32_t& r2, uint32_t& r3, uint32_t addr) {
    asm volatile("ldmatrix.sync.aligned.m8n8.x4.shared.b16 {%0,%1,%2,%3}, [%4];\n"
                 : "=r"(r0), "=r"(r1), "=r"(r2), "=r"(r3) : "r"(addr));
}
__device__ __forceinline__ void mma_tf32(float* c, const uint32_t* a, uint32_t b0, uint32_t b1) {
    asm volatile("mma.sync.aligned.m16n8k8.row.col.f32.tf32.tf32.f32 "
                 "{%0,%1,%2,%3}, {%4,%5,%6,%7}, {%8,%9}, {%0,%1,%2,%3};\n"
                 : "+f"(c[0]), "+f"(c[1]), "+f"(c[2]), "+f"(c[3])
                 : "r"(a[0]), "r"(a[1]), "r"(a[2]), "r"(a[3]), "r"(b0), "r"(b1));
}

// ---------------- feature build + grid index ----------------
__global__ void feat_kernel(const float* __restrict__ x) {
    int i = blockIdx.x * blockDim.x + threadIdx.x;
    if (i >= NP) return;
    const float* xr = x + (size_t)i * 24;
    float lat = xr[0];
    if (lat == -90.0f) lat += 0.0001f;
    float lon = xr[1];
    float t   = xr[2];

    int lati = (int)floorf(90.0f - lat);
    int loni = (int)fmodf(180.0f + floorf(lon + 180.0f), 360.0f);
    g_flat[i] = lati * GW + loni;

    float* f = g_feat + (size_t)i * 80;
    f[0] = lat * (1.0f/90.0f);
    f[1] = lon * (1.0f/180.0f);
    f[2] = t   * (1.0f/12.0f);
    #pragma unroll
    for (int j = 3; j < 24; j++) f[j] = xr[j];

    float p0 = -lat - floorf(-lat);   // mod(-lat, 1)
    float p1 =  lon - floorf(lon);    // mod(lon, 1)
    float p2 =  t + 1.0f;
    f[24] = p0; f[25] = p1; f[26] = p2;
    float p[3] = {p0, p1, p2};
    #pragma unroll
    for (int c = 0; c < 3; c++) {
        float fr = 3.14159274101257324f;  // fp32 pi; *2^k stays exact
        #pragma unroll
        for (int k = 0; k < 8; k++) {
            float ang = p[c] * fr;
            f[27 + c*8 + k] = sinf(ang);
            f[51 + c*8 + k] = cosf(ang);
            fr *= 2.0f;
        }
    }
    f[75] = 0.0f; f[76] = 0.0f; f[77] = 0.0f; f[78] = 0.0f; f[79] = 0.0f;
}

// ---------------- weight transpose + tf32 round: dst[n*Kp+k] = tf32(src[k*N+n]) ----------------
__global__ void transpose_round(const float* __restrict__ src, float* __restrict__ dst,
                                int K, int N, int Kp) {
    int idx = blockIdx.x * blockDim.x + threadIdx.x;
    if (idx >= N * Kp) return;
    int n = idx / Kp, k = idx - n * Kp;
    float v = (k < K) ? src[(size_t)k * N + n] : 0.0f;
    dst[idx] = __uint_as_float(f2tf32(v));
}

// ---------------- tensor-core GEMM: C = A(MxK) @ Bt^T + bias, epilogues ----------------
// A row-major [M][lda], Bt row-major [N][ldb] (= B transposed, tf32-pre-rounded).
// Tile: 128x128x32, 256 threads (8 warps, 4x2), warp tile 32x64 of m16n8k8 mma.
// EPI: 0 = bias, 1 = bias + residual R, 2 = bias + tanh-GELU.
#define SMS 36                      // smem row stride (floats): conflict-free ldmatrix
#define STG (128*SMS)               // floats per stage per operand

template<int EPI>
__global__ void gemm_tc(const float* __restrict__ A, const float* __restrict__ Bt,
                        const float* __restrict__ bias, const float* __restrict__ R,
                        float* __restrict__ C, int M, int N, int K, int lda, int ldb) {
    extern __shared__ float sm[];
    float* As = sm;            // [2][128][SMS]
    float* Bs = sm + 2*STG;    // [2][128][SMS]

    const int tid  = threadIdx.x;
    const int lane = tid & 31;
    const int w    = tid >> 5;
    const int wm   = w & 3;     // warp row (4)
    const int wn   = w >> 2;    // warp col (2)
    const int bm   = blockIdx.y * 128;
    const int bn   = blockIdx.x * 128;

    const uint32_t sA = (uint32_t)__cvta_generic_to_shared(As);
    const uint32_t sB = (uint32_t)__cvta_generic_to_shared(Bs);

    float acc[2][8][4];
    #pragma unroll
    for (int mi = 0; mi < 2; mi++)
        #pragma unroll
        for (int ni = 0; ni < 8; ni++)
            #pragma unroll
            for (int r = 0; r < 4; r++) acc[mi][ni][r] = 0.0f;

    // ldmatrix per-lane address components
    const int lrow = (lane & 7) + ((lane >> 3) & 1) * 8;  // row within 16-row group
    const int lkof = ((lane >> 4) & 1) * 4;               // k offset 0 or 4
    const int ra0  = wm * 32 + lrow;                      // A row (+ mi*16)
    const int rb0  = wn * 64 + lrow;                      // B n-row (+ npair*16)

    const int niter = (K + 31) >> 5;

    // stage loader
    auto load_stage = [&](int s, int k0) {
        #pragma unroll
        for (int l = 0; l < 4; l++) {
            int c   = tid + l * 256;       // 0..1023
            int row = c >> 3;
            int kc  = (c & 7) << 2;
            bool pa = (bm + row < M) && (k0 + kc < K);
            const float* srcA = pa ? (A + (size_t)(bm + row) * lda + k0 + kc) : A;
            cpasync16(sA + (uint32_t)((s * STG + row * SMS + kc) * 4), srcA, pa);
        }
        #pragma unroll
        for (int l = 0; l < 4; l++) {
            int c   = tid + l * 256;
            int row = c >> 3;
            int kc  = (c & 7) << 2;
            bool pb = (k0 + kc < K);
            const float* srcB = pb ? (Bt + (size_t)(bn + row) * ldb + k0 + kc) : Bt;
            cpasync16(sB + (uint32_t)((s * STG + row * SMS + kc) * 4), srcB, pb);
        }
        cp_commit();
    };

    load_stage(0, 0);

    for (int it = 0; it < niter; it++) {
        if (it + 1 < niter) {
            load_stage((it + 1) & 1, (it + 1) * 32);
            asm volatile("cp.async.wait_group 1;\n" ::);
        } else {
            asm volatile("cp.async.wait_group 0;\n" ::);
        }
        __syncthreads();

        const int s = it & 1;
        #pragma unroll
        for (int kk = 0; kk < 32; kk += 8) {
            uint32_t a[2][4];
            #pragma unroll
            for (int mi = 0; mi < 2; mi++) {
                uint32_t addr = sA + (uint32_t)((s * STG + (ra0 + mi * 16) * SMS + kk + lkof) * 4);
                ldm4(a[mi][0], a[mi][1], a[mi][2], a[mi][3], addr);
                #pragma unroll
                for (int r = 0; r < 4; r++) a[mi][r] = f2tf32(__uint_as_float(a[mi][r]));
            }
            uint32_t b0[8], b1[8];
            #pragma unroll
            for (int np = 0; np < 4; np++) {
                uint32_t addr = sB + (uint32_t)((s * STG + (rb0 + np * 16) * SMS + kk + lkof) * 4);
                uint32_t r0, r1, r2, r3;
                ldm4(r0, r1, r2, r3, addr);
                b0[2*np] = r0; b0[2*np+1] = r1;
                b1[2*np] = r2; b1[2*np+1] = r3;
            }
            #pragma unroll
            for (int mi = 0; mi < 2; mi++)
                #pragma unroll
                for (int ni = 0; ni < 8; ni++)
                    mma_tf32(acc[mi][ni], a[mi], b0[ni], b1[ni]);
        }
        __syncthreads();
    }

    // epilogue
    const int row0 = bm + wm * 32 + (lane >> 2);
    const int col0 = bn + wn * 64 + (lane & 3) * 2;
    #pragma unroll
    for (int mi = 0; mi < 2; mi++) {
        #pragma unroll
        for (int half = 0; half < 2; half++) {
            int gm = row0 + mi * 16 + half * 8;
            if (gm >= M) continue;
            #pragma unroll
            for (int ni = 0; ni < 8; ni++) {
                int gn = col0 + ni * 8;
                float v0 = acc[mi][ni][half*2 + 0] + bias[gn];
                float v1 = acc[mi][ni][half*2 + 1] + bias[gn + 1];
                if (EPI == 1) {
                    const float2 rr = *(const float2*)(R + (size_t)gm * N + gn);
                    v0 += rr.x; v1 += rr.y;
                }
                if (EPI == 2) {
                    float u = v0;
                    v0 = 0.5f * u * (1.0f + tanhf(0.7978845608028654f * (u + 0.044715f * u * u * u)));
                    u = v1;
                    v1 = 0.5f * u * (1.0f + tanhf(0.7978845608028654f * (u + 0.044715f * u * u * u)));
                }
                float2 o; o.x = v0; o.y = v1;
                *(float2*)(C + (size_t)gm * N + gn) = o;
            }
        }
    }
}

// ---------------- LayerNorm: one warp per token (128 dims) ----------------
__global__ void ln_kernel(const float* __restrict__ h, float* __restrict__ out,
                          const float* __restrict__ s, const float* __restrict__ b) {
    int gthread = blockIdx.x * blockDim.x + threadIdx.x;
    int token = gthread >> 5;
    int lane  = threadIdx.x & 31;
    if (token >= NTOK) return;
    const float4* row = (const float4*)(h + (size_t)token * 128);
    float4 v = row[lane];
    float sum = v.x + v.y + v.z + v.w;
    float sq  = v.x*v.x + v.y*v.y + v.z*v.z + v.w*v.w;
    #pragma unroll
    for (int o = 16; o > 0; o >>= 1) {
        sum += __shfl_xor_sync(0xffffffffu, sum, o);
        sq  += __shfl_xor_sync(0xffffffffu, sq,  o);
    }
    float mean = sum * (1.0f/128.0f);
    float var  = sq  * (1.0f/128.0f) - mean * mean;
    float r = rsqrtf(var + 1e-5f);
    float4 sv = ((const float4*)s)[lane];
    float4 bv = ((const float4*)b)[lane];
    float4 o4;
    o4.x = (v.x - mean) * r * sv.x + bv.x;
    o4.y = (v.y - mean) * r * sv.y + bv.y;
    o4.z = (v.z - mean) * r * sv.z + bv.z;
    o4.w = (v.w - mean) * r * sv.w + bv.w;
    ((float4*)(out + (size_t)token * 128))[lane] = o4;
}

// ---------------- attention: one thread per (point, head); 4 tokens, dh=16 ----------------
__global__ void attn_kernel() {
    int idx = blockIdx.x * blockDim.x + threadIdx.x;
    if (idx >= NP * 8) return;
    int n = idx >> 3;
    int h = idx & 7;
    const float* base = g_qkv + (size_t)n * 1536 + h * 16;  // token stride 384
    #pragma unroll
    for (int qi = 0; qi < 4; qi++) {
        float q[16];
        const float4* qp = (const float4*)(base + qi * 384);
        #pragma unroll
        for (int c = 0; c < 4; c++) {
            float4 t = qp[c];
            q[c*4+0] = t.x; q[c*4+1] = t.y; q[c*4+2] = t.z; q[c*4+3] = t.w;
        }
        float sc[4];
        float mx = -1e30f;
        #pragma unroll
        for (int ki = 0; ki < 4; ki++) {
            const float4* kp = (const float4*)(base + 128 + ki * 384);
            float s = 0.0f;
            #pragma unroll
            for (int c = 0; c < 4; c++) {
                float4 t = kp[c];
                s += q[c*4+0]*t.x + q[c*4+1]*t.y + q[c*4+2]*t.z + q[c*4+3]*t.w;
            }
            s *= 0.25f;   // 1/sqrt(16)
            sc[ki] = s;
            mx = fmaxf(mx, s);
        }
        float sum = 0.0f;
        #pragma unroll
        for (int ki = 0; ki < 4; ki++) { sc[ki] = expf(sc[ki] - mx); sum += sc[ki]; }
        float inv = 1.0f / sum;
        float acc[16];
        #pragma unroll
        for (int d = 0; d < 16; d++) acc[d] = 0.0f;
        #pragma unroll
        for (int ki = 0; ki < 4; ki++) {
            float w = sc[ki] * inv;
            const float4* vp = (const float4*)(base + 256 + ki * 384);
            #pragma unroll
            for (int c = 0; c < 4; c++) {
                float4 t = vp[c];
                acc[c*4+0] += w * t.x; acc[c*4+1] += w * t.y;
                acc[c*4+2] += w * t.z; acc[c*4+3] += w * t.w;
            }
        }
        float4* op = (float4*)(g_o + (size_t)(n * 4 + qi) * 128 + h * 16);
        #pragma unroll
        for (int c = 0; c < 4; c++) {
            float4 t;
            t.x = acc[c*4+0]; t.y = acc[c*4+1]; t.z = acc[c*4+2]; t.w = acc[c*4+3];
            op[c] = t;
        }
    }
}

// ---------------- segment mean ----------------
__global__ void zero_kernel(float* __restrict__ out) {
    int i = blockIdx.x * blockDim.x + threadIdx.x;
    if (i < NCELL * CLN) out[i] = 0.0f;
    else if (i < NCELL * CLN + NCELL) g_cnt[i - NCELL * CLN] = 0.0f;
}

__global__ void scatter_kernel(float* __restrict__ out) {
    int idx = blockIdx.x * blockDim.x + threadIdx.x;
    if (idx >= NP * 512) return;
    int n = idx >> 9;
    int j = idx & 511;
    int cell = g_flat[n];
    atomicAdd(out + (size_t)cell * 512 + j, g_y[idx]);
    if (j == 0) atomicAdd(&g_cnt[cell], 1.0f);
}

__global__ void div_kernel(float* __restrict__ out) {
    int i = blockIdx.x * blockDim.x + threadIdx.x;
    if (i >= NCELL * 512) return;
    out[i] *= 1.0f / fmaxf(g_cnt[i >> 9], 1.0f);
}

// ---------------- driver ----------------
extern "C" void kernel_launch(void* const* d_in, const int* in_sizes, int n_in,
                              void* d_out, int out_size) {
    const float* x      = (const float*)d_in[0];
    const float* W_emb  = (const float*)d_in[1];
    const float* b_emb  = (const float*)d_in[2];
    const float* ln1_s  = (const float*)d_in[3];
    const float* ln1_b  = (const float*)d_in[4];
    const float* Wqkv   = (const float*)d_in[5];
    const float* bqkv   = (const float*)d_in[6];
    const float* Wo     = (const float*)d_in[7];
    const float* bo     = (const float*)d_in[8];
    const float* ln2_s  = (const float*)d_in[9];
    const float* ln2_b  = (const float*)d_in[10];
    const float* Wf1    = (const float*)d_in[11];
    const float* bf1    = (const float*)d_in[12];
    const float* Wf2    = (const float*)d_in[13];
    const float* bf2    = (const float*)d_in[14];
    const float* W_comb = (const float*)d_in[15];
    const float* b_comb = (const float*)d_in[16];
    float* out = (float*)d_out;

    float *p_feat, *p_h, *p_a, *p_qkv, *p_o, *p_gel, *p_y, *p_wt;
    cudaGetSymbolAddress((void**)&p_feat, g_feat);
    cudaGetSymbolAddress((void**)&p_h,    g_h);
    cudaGetSymbolAddress((void**)&p_a,    g_a);
    cudaGetSymbolAddress((void**)&p_qkv,  g_qkv);
    cudaGetSymbolAddress((void**)&p_o,    g_o);
    cudaGetSymbolAddress((void**)&p_gel,  g_gel);
    cudaGetSymbolAddress((void**)&p_y,    g_y);
    cudaGetSymbolAddress((void**)&p_wt,   g_wt);

    const int SMEM = 4 * (4 * STG);   // 73728 bytes
    static bool attr_done = false;
    if (!attr_done) {
        cudaFuncSetAttribute(gemm_tc<0>, cudaFuncAttributeMaxDynamicSharedMemorySize, SMEM);
        cudaFuncSetAttribute(gemm_tc<1>, cudaFuncAttributeMaxDynamicSharedMemorySize, SMEM);
        cudaFuncSetAttribute(gemm_tc<2>, cudaFuncAttributeMaxDynamicSharedMemorySize, SMEM);
        attr_done = true;
    }

    const int TB = 256;

    // weight transposes (tf32-rounded), offsets into g_wt
    float* wembT  = p_wt + 0;                       // [512][80]
    float* wqkvT0 = p_wt + 40960;                   // [384][128]
    float* wqkvT1 = p_wt + 90112;
    float* woT0   = p_wt + 139264;                  // [128][128]
    float* woT1   = p_wt + 155648;
    float* wf1T0  = p_wt + 172032;                  // [512][128]
    float* wf1T1  = p_wt + 237568;
    float* wf2T0  = p_wt + 303104;                  // [128][512]
    float* wf2T1  = p_wt + 368640;
    float* wcombT = p_wt + 434176;                  // [512][512]

    transpose_round<<<(512*80 + TB-1)/TB, TB>>>(W_emb, wembT, 75, 512, 80);
    transpose_round<<<(384*128 + TB-1)/TB, TB>>>(Wqkv,            wqkvT0, 128, 384, 128);
    transpose_round<<<(384*128 + TB-1)/TB, TB>>>(Wqkv + 128*384,  wqkvT1, 128, 384, 128);
    transpose_round<<<(128*128 + TB-1)/TB, TB>>>(Wo,              woT0,   128, 128, 128);
    transpose_round<<<(128*128 + TB-1)/TB, TB>>>(Wo + 128*128,    woT1,   128, 128, 128);
    transpose_round<<<(512*128 + TB-1)/TB, TB>>>(Wf1,             wf1T0,  128, 512, 128);
    transpose_round<<<(512*128 + TB-1)/TB, TB>>>(Wf1 + 128*512,   wf1T1,  128, 512, 128);
    transpose_round<<<(128*512 + TB-1)/TB, TB>>>(Wf2,             wf2T0,  512, 128, 512);
    transpose_round<<<(128*512 + TB-1)/TB, TB>>>(Wf2 + 512*128,   wf2T1,  512, 128, 512);
    transpose_round<<<(512*512 + TB-1)/TB, TB>>>(W_comb,          wcombT, 512, 512, 512);

    // 1) features + grid indices
    feat_kernel<<<(NP + TB - 1) / TB, TB>>>(x);

    // 2) embedding: feat(NP x 80) @ W_emb -> h
    {
        dim3 grid(512 / 128, (NP + 127) / 128);
        gemm_tc<0><<<grid, TB, SMEM>>>(p_feat, wembT, b_emb, nullptr, p_h, NP, 512, 80, 80, 80);
    }

    // 3) transformer layers
    const float* wqkvT[2] = {wqkvT0, wqkvT1};
    const float* woT[2]   = {woT0, woT1};
    const float* wf1T[2]  = {wf1T0, wf1T1};
    const float* wf2T[2]  = {wf2T0, wf2T1};
    for (int i = 0; i < 2; i++) {
        ln_kernel<<<(NTOK * 32 + TB - 1) / TB, TB>>>(p_h, p_a, ln1_s + i * 128, ln1_b + i * 128);
        {
            dim3 grid(384 / 128, (NTOK + 127) / 128);
            gemm_tc<0><<<grid, TB, SMEM>>>(p_a, wqkvT[i], bqkv + i * 384, nullptr,
                                           p_qkv, NTOK, 384, 128, 128, 128);
        }
        attn_kernel<<<(NP * 8 + TB - 1) / TB, TB>>>();
        {
            dim3 grid(1, (NTOK + 127) / 128);
            gemm_tc<1><<<grid, TB, SMEM>>>(p_o, woT[i], bo + i * 128, p_h,
                                           p_h, NTOK, 128, 128, 128, 128);
        }
        ln_kernel<<<(NTOK * 32 + TB - 1) / TB, TB>>>(p_h, p_a, ln2_s + i * 128, ln2_b + i * 128);
        {
            dim3 grid(512 / 128, (NTOK + 127) / 128);
            gemm_tc<2><<<grid, TB, SMEM>>>(p_a, wf1T[i], bf1 + i * 512, nullptr,
                                           p_gel, NTOK, 512, 128, 128, 128);
        }
        {
            dim3 grid(1, (NTOK + 127) / 128);
            gemm_tc<1><<<grid, TB, SMEM>>>(p_gel, wf2T[i], bf2 + i * 128, p_h,
                                           p_h, NTOK, 128, 512, 512, 512);
        }
    }

    // 4) head: h(NP x 512) @ W_comb -> y
    {
        dim3 grid(512 / 128, (NP + 127) / 128);
        gemm_tc<0><<<grid, TB, SMEM>>>(p_h, wcombT, b_comb, nullptr, p_y, NP, 512, 512, 512, 512);
    }

    // 5) segment mean into grid
    zero_kernel<<<(NCELL * CLN + NCELL + TB - 1) / TB, TB>>>(out);
    scatter_kernel<<<(NP * 512 + TB - 1) / TB, TB>>>(out);
    div_kernel<<<(NCELL * 512 + TB - 1) / TB, TB>>>(out);
}